// round 1
// baseline (speedup 1.0000x reference)
#include <cuda_runtime.h>
#include <cuda_bf16.h>
#include <math.h>
#include <stdint.h>

// Problem constants (fixed by reference)
#define N_SEQ   4096
#define N_DOCS  512
#define EMBD    300
#define HID     256
#define GATES   1024        // 4*HID
#define T_COL   64
#define T_ROW   16

// Tiling
#define MCH     32          // sequences per block
#define NKT     36          // k-tiles of 16 -> 576 (556 real + pad)
#define AK      584         // padded A row stride in bf16 elems (292 words, !=0 mod 32 banks)
#define AKW     292

// smem carve offsets (bytes)
#define SM_AS    0
#define SM_CS    (MCH*AK*2)                 // 37376
#define SM_BIAS  (SM_CS + MCH*257*4)        // 37376+32896 = 70272
#define SM_LENS  (SM_BIAS + GATES*4)        // 74368
#define SM_TOKS  (SM_LENS + 128)            // 74496
#define SMEM_BYTES (SM_TOKS + 128)          // 74624

// ---------------- device scratch (no allocs allowed) ----------------
// B fragments: [mat][kt][ntile(128)][lane] as uint2 (b0,b1), bf16x2 packed
__device__ uint2  g_Bpack[2][NKT][128][32];     // 2.36 MB
__device__ float  g_bias[2][GATES];
__device__ float  g_acc[3][N_DOCS][HID];        // 1.5 MB doc accumulators

// ---------------- helpers ----------------
__device__ __forceinline__ float ftanh(float x) {
    float y; asm("tanh.approx.f32 %0, %1;" : "=f"(y) : "f"(x)); return y;
}
__device__ __forceinline__ float fsigm(float x) {
    return 0.5f * ftanh(0.5f * x) + 0.5f;
}
__device__ __forceinline__ void mma16816(float* c, const uint32_t* a, uint2 b) {
    asm volatile(
        "mma.sync.aligned.m16n8k16.row.col.f32.bf16.bf16.f32 "
        "{%0,%1,%2,%3},{%4,%5,%6,%7},{%8,%9},{%0,%1,%2,%3};"
        : "+f"(c[0]), "+f"(c[1]), "+f"(c[2]), "+f"(c[3])
        : "r"(a[0]), "r"(a[1]), "r"(a[2]), "r"(a[3]), "r"(b.x), "r"(b.y));
}

// ---------------- init: zero accumulators + output ----------------
__global__ void init_kernel(float* out) {
    int i = blockIdx.x * blockDim.x + threadIdx.x;
    if (i == 0) *out = 0.f;
    if (i < 3 * N_DOCS * HID) (&g_acc[0][0][0])[i] = 0.f;
}

// ---------------- prep: pack weights into mma B-fragment layout ----------------
// permuted column j' : gate = j'&3 (i,f,g,o), unit u = j'>>2 ; orig col = gate*256+u
__global__ void prep_kernel(const float* cWih, const float* cWhh,
                            const float* cbih, const float* cbhh,
                            const float* rWih, const float* rWhh,
                            const float* rbih, const float* rbhh) {
    int idx = blockIdx.x * blockDim.x + threadIdx.x;   // < 2*36*128*32 = 294912
    int lane = idx & 31;
    int ntg  = (idx >> 5) & 127;
    int q    = idx >> 12;            // mat*36 + kt
    int kt   = q % NKT;
    int mat  = q / NKT;
    const float* Wih = mat ? rWih : cWih;
    const float* Whh = mat ? rWhh : cWhh;

    int tg = lane & 3, gg = lane >> 2;
    int jp = ntg * 8 + gg;                       // permuted col
    int jo = (jp & 3) * 256 + (jp >> 2);         // original col
    int k0 = kt * 16 + 2 * tg;

    float v0, v1, v2, v3;
    {
        // fetch Wc(k, jo): k<300 -> Wih, k<556 -> Whh, else 0
        int ks[4] = {k0, k0 + 1, k0 + 8, k0 + 9};
        float vv[4];
        #pragma unroll
        for (int i = 0; i < 4; i++) {
            int k = ks[i];
            float f = 0.f;
            if (k < EMBD)            f = Wih[jo * EMBD + k];
            else if (k < EMBD + HID) f = Whh[jo * HID + (k - EMBD)];
            vv[i] = f;
        }
        v0 = vv[0]; v1 = vv[1]; v2 = vv[2]; v3 = vv[3];
    }
    __nv_bfloat162 p0 = __halves2bfloat162(__float2bfloat16(v0), __float2bfloat16(v1));
    __nv_bfloat162 p1 = __halves2bfloat162(__float2bfloat16(v2), __float2bfloat16(v3));
    uint2 w2;
    w2.x = *reinterpret_cast<uint32_t*>(&p0);
    w2.y = *reinterpret_cast<uint32_t*>(&p1);
    g_Bpack[mat][kt][ntg][lane] = w2;

    if (idx < 2 * GATES) {
        int bm = idx >> 10, jb = idx & 1023;
        int jbo = (jb & 3) * 256 + (jb >> 2);
        const float* bih = bm ? rbih : cbih;
        const float* bhh = bm ? rbhh : cbhh;
        g_bias[bm][jb] = bih[jbo] + bhh[jbo];
    }
}

// ---------------- main fused LSTM kernel ----------------
__global__ void __launch_bounds__(256, 1)
lstm_kernel(const int* colT, const int* rowT, const int* negT,
            const int* clen, const int* rlen, const int* nlen,
            const int* cref, const int* rref, const int* nref,
            const float* emb) {
    extern __shared__ char smem[];
    __nv_bfloat16* As   = (__nv_bfloat16*)(smem + SM_AS);    // [MCH][AK]
    float*         Cs   = (float*)(smem + SM_CS);            // [MCH][257]
    float*         bias = (float*)(smem + SM_BIAS);          // [1024]
    int*           lensS= (int*)(smem + SM_LENS);            // [32]
    int*           toksS= (int*)(smem + SM_TOKS);            // [32]

    int bid = blockIdx.x;
    int task = bid >> 7;         // 0=col, 1=row, 2=neg (128 chunks each)
    int chunk = bid & 127;
    int n0 = chunk * MCH;

    const int* toks; const int* lens; const int* refs; int T; int mat;
    if (task == 0)      { toks = colT; lens = clen; refs = cref; T = T_COL; mat = 0; }
    else if (task == 1) { toks = rowT; lens = rlen; refs = rref; T = T_ROW; mat = 1; }
    else                { toks = negT; lens = nlen; refs = nref; T = T_ROW; mat = 1; }

    int tid = threadIdx.x;
    int w = tid >> 5, lane = tid & 31;
    int tg = lane & 3, gg = lane >> 2;

    // --- init smem ---
    for (int i = tid; i < GATES; i += 256) bias[i] = g_bias[mat][i];
    for (int i = tid; i < MCH * 257; i += 256) Cs[i] = 0.f;
    for (int i = tid; i < MCH * (AK - EMBD); i += 256) {  // zero h region + pad
        int m = i / (AK - EMBD), k = EMBD + i % (AK - EMBD);
        As[m * AK + k] = __float2bfloat16(0.f);
    }
    if (tid < MCH) lensS[tid] = lens[n0 + tid];
    __syncthreads();

    int maxlen = 0;
    #pragma unroll
    for (int i = 0; i < MCH; i++) maxlen = max(maxlen, lensS[i]);

    const uint32_t* Aw = (const uint32_t*)As;
    // per-thread B base: this warp's 16 n-tiles start at ntile w*16
    const uint2* Bp = &g_Bpack[mat][0][0][0] + (size_t)w * 16 * 32 + lane;
    const int a_base = gg * AKW + tg;   // word index of a0 at kt=0, mt=0

    const float4* emb4 = (const float4*)emb;

    for (int t = 0; t < maxlen; t++) {
        if (tid < MCH) toksS[tid] = toks[(n0 + tid) * T + t];
        __syncthreads();   // toks visible; prev epilogue/mma done

        // gather x: 8 threads per sequence row, float4 loads
        {
            int m = tid >> 3, ts = tid & 7;
            const float4* erow = emb4 + (size_t)toksS[m] * (EMBD / 4);
            __nv_bfloat16* arow = As + m * AK;
            for (int kk = ts; kk < EMBD / 4; kk += 8) {
                float4 v = __ldg(&erow[kk]);
                __nv_bfloat162 p0 = __halves2bfloat162(__float2bfloat16(v.x), __float2bfloat16(v.y));
                __nv_bfloat162 p1 = __halves2bfloat162(__float2bfloat16(v.z), __float2bfloat16(v.w));
                uint2 w2;
                w2.x = *reinterpret_cast<uint32_t*>(&p0);
                w2.y = *reinterpret_cast<uint32_t*>(&p1);
                *reinterpret_cast<uint2*>(arow + kk * 4) = w2;
            }
        }
        __syncthreads();   // x visible

        // --- GEMM: [32,576] @ [576, 128-per-warp] ---
        float acc[2][16][4];
        #pragma unroll
        for (int mt = 0; mt < 2; mt++)
            #pragma unroll
            for (int nt = 0; nt < 16; nt++)
                #pragma unroll
                for (int i = 0; i < 4; i++) acc[mt][nt][i] = 0.f;

        #pragma unroll 4
        for (int kt = 0; kt < NKT; kt++) {
            uint32_t a[2][4];
            int ab = a_base + kt * 8;
            #pragma unroll
            for (int mt = 0; mt < 2; mt++) {
                int o = ab + mt * 16 * AKW;
                a[mt][0] = Aw[o];
                a[mt][1] = Aw[o + 8 * AKW];
                a[mt][2] = Aw[o + 4];
                a[mt][3] = Aw[o + 8 * AKW + 4];
            }
            const uint2* bk = Bp + (size_t)kt * 128 * 32;
            #pragma unroll
            for (int nt = 0; nt < 16; nt++) {
                uint2 b = __ldg(bk + nt * 32);
                mma16816(acc[0][nt], a[0], b);
                mma16816(acc[1][nt], a[1], b);
            }
        }
        __syncthreads();   // all mma reads of h done before epilogue writes

        // --- epilogue: bias, lane-pair gate exchange, LSTM cell update ---
        bool ev = !(tg & 1);
        #pragma unroll
        for (int mt = 0; mt < 2; mt++) {
            #pragma unroll
            for (int nt = 0; nt < 16; nt++) {
                int jc = (w << 7) + (nt << 3) + (tg << 1);
                float b0 = bias[jc], b1 = bias[jc + 1];
                float x0 = acc[mt][nt][0] + b0;
                float x1 = acc[mt][nt][1] + b1;
                float x2 = acc[mt][nt][2] + b0;
                float x3 = acc[mt][nt][3] + b1;
                float y0 = __shfl_xor_sync(0xffffffffu, x0, 1);
                float y1 = __shfl_xor_sync(0xffffffffu, x1, 1);
                float y2 = __shfl_xor_sync(0xffffffffu, x2, 1);
                float y3 = __shfl_xor_sync(0xffffffffu, x3, 1);
                // even lane: row g (i=x0,f=x1,g=y0,o=y1); odd: row g+8 (i=y2,f=y3,g=x2,o=x3)
                float pi = ev ? x0 : y2;
                float pf = ev ? x1 : y3;
                float pg = ev ? y0 : x2;
                float po = ev ? y1 : x3;
                int mrow = (mt << 4) + gg + (ev ? 0 : 8);
                int u = (w << 5) + (nt << 1) + (tg >> 1);
                if (t < lensS[mrow]) {
                    float i_ = fsigm(pi), f_ = fsigm(pf), o_ = fsigm(po), g_ = ftanh(pg);
                    float cn = f_ * Cs[mrow * 257 + u] + i_ * g_;
                    Cs[mrow * 257 + u] = cn;
                    As[mrow * AK + EMBD + u] = __float2bfloat16(o_ * ftanh(cn));
                }
            }
        }
        // next iteration's first __syncthreads orders these writes
    }

    // --- scatter final h into doc accumulators ---
    __syncthreads();
    if (tid < MCH) toksS[tid] = refs[n0 + tid];
    __syncthreads();
    float* accb = &g_acc[task][0][0];
    for (int idx = tid; idx < MCH * HID; idx += 256) {
        int m = idx >> 8, u = idx & 255;
        float h = __bfloat162float(As[m * AK + EMBD + u]);
        atomicAdd(&accb[toksS[m] * HID + u], h);
    }
}

// ---------------- loss: per-doc dots + BPR sum ----------------
__global__ void loss_kernel(float* out) {
    int d = blockIdx.x, u = threadIdx.x;   // 512 blocks x 256 threads
    float cv = g_acc[0][d][u], rv = g_acc[1][d][u], nv = g_acc[2][d][u];
    float p = cv * rv, q = cv * nv;
    #pragma unroll
    for (int o = 16; o; o >>= 1) {
        p += __shfl_xor_sync(0xffffffffu, p, o);
        q += __shfl_xor_sync(0xffffffffu, q, o);
    }
    __shared__ float sp[8], sq[8];
    int w = threadIdx.x >> 5, l = threadIdx.x & 31;
    if (l == 0) { sp[w] = p; sq[w] = q; }
    __syncthreads();
    if (threadIdx.x == 0) {
        float P = 0.f, Q = 0.f;
        #pragma unroll
        for (int i = 0; i < 8; i++) { P += sp[i]; Q += sq[i]; }
        float x = P - Q;
        float lz = fmaxf(-x, 0.f) + log1pf(expf(-fabsf(x)));   // -logsigmoid(x)
        if (d == 0) lz += (float)((N_SEQ - N_DOCS) * 0.6931471805599453);
        atomicAdd(out, lz);
    }
}

// ---------------- launch ----------------
extern "C" void kernel_launch(void* const* d_in, const int* in_sizes, int n_in,
                              void* d_out, int out_size) {
    const int*   col   = (const int*)d_in[0];
    const int*   row   = (const int*)d_in[1];
    const int*   rng   = (const int*)d_in[2];
    const int*   clen  = (const int*)d_in[3];
    const int*   rlen  = (const int*)d_in[4];
    const int*   nlen  = (const int*)d_in[5];
    const int*   cref  = (const int*)d_in[6];
    const int*   rref  = (const int*)d_in[7];
    const int*   nref  = (const int*)d_in[8];
    const float* emb   = (const float*)d_in[9];
    const float* cWih  = (const float*)d_in[10];
    const float* cWhh  = (const float*)d_in[11];
    const float* cbih  = (const float*)d_in[12];
    const float* cbhh  = (const float*)d_in[13];
    const float* rWih  = (const float*)d_in[14];
    const float* rWhh  = (const float*)d_in[15];
    const float* rbih  = (const float*)d_in[16];
    const float* rbhh  = (const float*)d_in[17];
    float* out = (float*)d_out;

    cudaFuncSetAttribute(lstm_kernel, cudaFuncAttributeMaxDynamicSharedMemorySize, SMEM_BYTES);

    init_kernel<<<(3 * N_DOCS * HID + 255) / 256, 256>>>(out);
    prep_kernel<<<(2 * NKT * 128 * 32) / 256, 256>>>(cWih, cWhh, cbih, cbhh,
                                                     rWih, rWhh, rbih, rbhh);
    lstm_kernel<<<384, 256, SMEM_BYTES>>>(col, row, rng, clen, rlen, nlen,
                                          cref, rref, nref, emb);
    loss_kernel<<<N_DOCS, 256>>>(out);
}